// round 1
// baseline (speedup 1.0000x reference)
#include <cuda_runtime.h>
#include <cstdint>

// Gated delta-rule recurrent attention, single step.
// B=128, H=16, Dk=Dv=128.
// One CTA per (b,h): 2048 CTAs x 128 threads. Thread t owns state column v=t.
// State tile read once from HBM into registers (full unroll), written once.
// HBM traffic: 134 MB read + 134 MB write (+ ~3 MB small tensors) -> memory-bound.

#define BH   2048
#define DK   128
#define DV   128

__global__ __launch_bounds__(128, 3)
void delta_cell_kernel(const float* __restrict__ q,
                       const float* __restrict__ k,
                       const float* __restrict__ v,
                       const float* __restrict__ g,
                       const float* __restrict__ beta,
                       const float* __restrict__ state_in,
                       float* __restrict__ out,
                       float* __restrict__ state_out)
{
    const int bh = blockIdx.x;       // 0..2047  == b*H + h
    const int t  = threadIdx.x;      // 0..127   == column v

    __shared__ float ks[DK];
    __shared__ float qs[DK];

    // k/q vectors for this (b,h) into shared (broadcast-read later, conflict-free)
    ks[t] = k[bh * DK + t];
    qs[t] = q[bh * DK + t];
    __syncthreads();

    const float decay = expf(g[bh]);
    const float bet   = beta[bh];
    const float vt    = v[bh * DV + t];

    const float* __restrict__ st  = state_in  + (size_t)bh * DK * DV;
    float*       __restrict__ sto = state_out + (size_t)bh * DK * DV;

    // Pass over k-rows: load the thread's state column (coalesced 512B rows
    // across the CTA), decay it, and reduce against k to form kv_mem[t].
    // Column kept in registers so state is touched exactly once.
    float s[DK];
    float kv = 0.0f;
#pragma unroll
    for (int i = 0; i < DK; ++i) {
        float x = st[i * DV + t];
        x *= decay;
        s[i] = x;
        kv = fmaf(x, ks[i], kv);
    }

    const float delta = (vt - kv) * bet;

    // Update state column, write back, and reduce against q for the output.
    float acc = 0.0f;
#pragma unroll
    for (int i = 0; i < DK; ++i) {
        float sn = fmaf(ks[i], delta, s[i]);
        sto[i * DV + t] = sn;
        acc = fmaf(sn, qs[i], acc);
    }

    out[bh * DV + t] = acc;
}

extern "C" void kernel_launch(void* const* d_in, const int* in_sizes, int n_in,
                              void* d_out, int out_size)
{
    const float* q     = (const float*)d_in[0];  // (B,H,1,Dk)
    const float* k     = (const float*)d_in[1];  // (B,H,1,Dk)
    const float* v     = (const float*)d_in[2];  // (B,H,1,Dv)
    const float* g     = (const float*)d_in[3];  // (B,H,1)
    const float* beta  = (const float*)d_in[4];  // (B,H,1)
    const float* state = (const float*)d_in[5];  // (B,H,Dk,Dv)

    float* out       = (float*)d_out;            // first B*H*Dv floats
    float* state_out = out + (size_t)BH * DV;    // then B*H*Dk*Dv floats

    delta_cell_kernel<<<BH, 128>>>(q, k, v, g, beta, state, out, state_out);
}

// round 2
// speedup vs baseline: 1.2146x; 1.2146x over previous
#include <cuda_runtime.h>
#include <cstdint>

// Gated delta-rule recurrent attention, single step. B=128, H=16, Dk=Dv=128.
//
// One CTA per (b,h): 2048 CTAs x 512 threads.
// Thread (r, c) with r = tid>>5 (16 row groups), c = tid&31 (32 column quads)
// owns an 8-row x 4-col (float4) patch of the 128x128 state tile.
// State is loaded once (LDG.128, coalesced 512B per warp per row), kept in
// 32 registers/thread, and written once (STG.128). Cross-row-group reductions
// for delta (k-dot) and out (q-dot) go through small shared buffers.
//
// Regs ~60/thread -> 2 CTAs/SM = 32 warps (50% occ) vs 12 warps before.
// Goal: push DRAM from 63% toward saturation.

#define BH   2048
#define DK   128
#define DV   128

__global__ __launch_bounds__(512, 2)
void delta_cell_kernel(const float* __restrict__ q,
                       const float* __restrict__ k,
                       const float* __restrict__ v,
                       const float* __restrict__ g,
                       const float* __restrict__ beta,
                       const float* __restrict__ state_in,
                       float* __restrict__ out,
                       float* __restrict__ state_out)
{
    const int bh  = blockIdx.x;      // b*H + h
    const int tid = threadIdx.x;
    const int c   = tid & 31;        // column quad: cols 4c..4c+3
    const int r   = tid >> 5;        // row group:  rows 8r..8r+7

    __shared__ float  ks[DK];
    __shared__ float  qs[DK];
    __shared__ float4 red_kv [16][32];  // per-row-group kv partials
    __shared__ float4 red_out[16][32];  // per-row-group out partials

    if (tid < DK) {
        ks[tid] = k[bh * DK + tid];
        qs[tid] = q[bh * DK + tid];
    }
    __syncthreads();

    const float decay = expf(g[bh]);
    const float bet   = beta[bh];

    const float4* __restrict__ st  =
        (const float4*)(state_in  + (size_t)bh * DK * DV);
    float4* __restrict__ sto =
        (float4*)(state_out + (size_t)bh * DK * DV);

    // ---- Pass 1: load + decay the thread's 8x4 patch, partial k-dot ----
    float4 s[8];
    float4 kv = make_float4(0.f, 0.f, 0.f, 0.f);
#pragma unroll
    for (int j = 0; j < 8; ++j) {
        const int i = r * 8 + j;
        float4 x = st[i * 32 + c];      // warp reads 512B contiguous
        x.x *= decay; x.y *= decay; x.z *= decay; x.w *= decay;
        s[j] = x;
        const float kk = ks[i];
        kv.x = fmaf(x.x, kk, kv.x);
        kv.y = fmaf(x.y, kk, kv.y);
        kv.z = fmaf(x.z, kk, kv.z);
        kv.w = fmaf(x.w, kk, kv.w);
    }
    red_kv[r][c] = kv;
    __syncthreads();

    // ---- All threads reduce the 16 partials (redundant, avoids a barrier) ----
    float4 kvt = make_float4(0.f, 0.f, 0.f, 0.f);
#pragma unroll
    for (int j = 0; j < 16; ++j) {
        const float4 p = red_kv[j][c];
        kvt.x += p.x; kvt.y += p.y; kvt.z += p.z; kvt.w += p.w;
    }

    const float4 vt = ((const float4*)(v + (size_t)bh * DV))[c];
    float4 delta;
    delta.x = (vt.x - kvt.x) * bet;
    delta.y = (vt.y - kvt.y) * bet;
    delta.z = (vt.z - kvt.z) * bet;
    delta.w = (vt.w - kvt.w) * bet;

    // ---- Pass 2: update state, store, partial q-dot ----
    float4 acc = make_float4(0.f, 0.f, 0.f, 0.f);
#pragma unroll
    for (int j = 0; j < 8; ++j) {
        const int i = r * 8 + j;
        const float kk = ks[i];
        float4 sn;
        sn.x = fmaf(kk, delta.x, s[j].x);
        sn.y = fmaf(kk, delta.y, s[j].y);
        sn.z = fmaf(kk, delta.z, s[j].z);
        sn.w = fmaf(kk, delta.w, s[j].w);
        sto[i * 32 + c] = sn;           // warp writes 512B contiguous
        const float qq = qs[i];
        acc.x = fmaf(sn.x, qq, acc.x);
        acc.y = fmaf(sn.y, qq, acc.y);
        acc.z = fmaf(sn.z, qq, acc.z);
        acc.w = fmaf(sn.w, qq, acc.w);
    }
    red_out[r][c] = acc;
    __syncthreads();

    // ---- Row-group 0 finishes the q-dot and writes the output ----
    if (r == 0) {
        float4 o = make_float4(0.f, 0.f, 0.f, 0.f);
#pragma unroll
        for (int j = 0; j < 16; ++j) {
            const float4 p = red_out[j][c];
            o.x += p.x; o.y += p.y; o.z += p.z; o.w += p.w;
        }
        ((float4*)(out + (size_t)bh * DV))[c] = o;
    }
}

extern "C" void kernel_launch(void* const* d_in, const int* in_sizes, int n_in,
                              void* d_out, int out_size)
{
    const float* q     = (const float*)d_in[0];  // (B,H,1,Dk)
    const float* k     = (const float*)d_in[1];  // (B,H,1,Dk)
    const float* v     = (const float*)d_in[2];  // (B,H,1,Dv)
    const float* g     = (const float*)d_in[3];  // (B,H,1)
    const float* beta  = (const float*)d_in[4];  // (B,H,1)
    const float* state = (const float*)d_in[5];  // (B,H,Dk,Dv)

    float* out       = (float*)d_out;            // first B*H*Dv floats
    float* state_out = out + (size_t)BH * DV;    // then B*H*Dk*Dv floats

    delta_cell_kernel<<<BH, 512>>>(q, k, v, g, beta, state, out, state_out);
}

// round 5
// speedup vs baseline: 1.3195x; 1.0864x over previous
#include <cuda_runtime.h>
#include <cstdint>

// Gated delta-rule recurrent attention, single step. B=128, H=16, Dk=Dv=128.
//
// Round-5: column-split decomposition. delta[v] needs only a reduction over k,
// so the 128x128 state tile is split into 4 independent column slices of
// 128(k) x 32(v). Grid = 2048*4 = 8192 CTAs x 128 threads; each CTA owns one
// slice end-to-end with no cross-CTA communication.
//
// Rationale: round-2 showed DRAM=63%, L2=33%, issue=22% -- nothing saturated.
// With 2 fat CTAs/SM, barrier-separated load/compute/store phases leave DRAM
// request bubbles. 8 small independent CTAs/SM interleave their phases and
// keep the request stream full.
//
// Thread (rg, c4): rg = tid>>3 (16 row groups of 8 rows), c4 = tid&7
// (float4 column within the 32-col slice). State slice kept in 8 float4
// registers: read once (__ldcs, evict-first), written once.

#define BH   2048
#define DK   128
#define DV   128

__global__ __launch_bounds__(128, 8)
void delta_cell_kernel(const float* __restrict__ q,
                       const float* __restrict__ k,
                       const float* __restrict__ v,
                       const float* __restrict__ g,
                       const float* __restrict__ beta,
                       const float* __restrict__ state_in,
                       float* __restrict__ out,
                       float* __restrict__ state_out)
{
    const int bid = blockIdx.x;          // 0..8191
    const int bh  = bid >> 2;            // (b*H + h)
    const int cb  = bid & 3;             // column block: cols [cb*32, cb*32+32)
    const int tid = threadIdx.x;
    const int c4  = tid & 7;             // float4 col within slice (0..7)
    const int rg  = tid >> 3;            // row group (0..15), rows 8rg..8rg+7

    __shared__ float  ks[DK];
    __shared__ float  qs[DK];
    __shared__ float4 red_kv [16][8];
    __shared__ float4 red_out[16][8];

    ks[tid] = k[bh * DK + tid];
    qs[tid] = q[bh * DK + tid];
    __syncthreads();

    const float decay = expf(g[bh]);
    const float bet   = beta[bh];
    const float4 vt   = ((const float4*)(v + (size_t)bh * DV))[cb * 8 + c4];

    const float4* __restrict__ st4 =
        (const float4*)(state_in  + (size_t)bh * DK * DV);
    float4* __restrict__ sto4 =
        (float4*)(state_out + (size_t)bh * DK * DV);
    const int colbase = cb * 8 + c4;     // float4 column in the full 32-wide row

    // ---- Pass 1: load the thread's 8x4 patch (raw), partial k-dot ----
    float4 s[8];
    float4 kv = make_float4(0.f, 0.f, 0.f, 0.f);
#pragma unroll
    for (int j = 0; j < 8; ++j) {
        const int row = rg * 8 + j;
        const float4 x = __ldcs(&st4[row * 32 + colbase]);
        s[j] = x;
        const float kk = ks[row];
        kv.x = fmaf(x.x, kk, kv.x);
        kv.y = fmaf(x.y, kk, kv.y);
        kv.z = fmaf(x.z, kk, kv.z);
        kv.w = fmaf(x.w, kk, kv.w);
    }
    red_kv[rg][c4] = kv;
    __syncthreads();

    // Reduce the 16 row-group partials (redundantly in every thread)
    float4 kvt = make_float4(0.f, 0.f, 0.f, 0.f);
#pragma unroll
    for (int gg = 0; gg < 16; ++gg) {
        const float4 p = red_kv[gg][c4];
        kvt.x += p.x; kvt.y += p.y; kvt.z += p.z; kvt.w += p.w;
    }
    // kv_mem = decay * (state . k); delta = (v - kv_mem) * beta
    float4 delta;
    delta.x = (vt.x - decay * kvt.x) * bet;
    delta.y = (vt.y - decay * kvt.y) * bet;
    delta.z = (vt.z - decay * kvt.z) * bet;
    delta.w = (vt.w - decay * kvt.w) * bet;

    // ---- Pass 2: sn = decay*state + k*delta, store, partial q-dot ----
    float4 acc = make_float4(0.f, 0.f, 0.f, 0.f);
#pragma unroll
    for (int j = 0; j < 8; ++j) {
        const int row = rg * 8 + j;
        const float kk = ks[row];
        float4 sn;
        sn.x = fmaf(decay, s[j].x, kk * delta.x);
        sn.y = fmaf(decay, s[j].y, kk * delta.y);
        sn.z = fmaf(decay, s[j].z, kk * delta.z);
        sn.w = fmaf(decay, s[j].w, kk * delta.w);
        sto4[row * 32 + colbase] = sn;
        const float qq = qs[row];
        acc.x = fmaf(sn.x, qq, acc.x);
        acc.y = fmaf(sn.y, qq, acc.y);
        acc.z = fmaf(sn.z, qq, acc.z);
        acc.w = fmaf(sn.w, qq, acc.w);
    }
    red_out[rg][c4] = acc;
    __syncthreads();

    // Row-group 0 finishes the q-dot and writes this slice's output columns
    if (rg == 0) {
        float4 o = make_float4(0.f, 0.f, 0.f, 0.f);
#pragma unroll
        for (int gg = 0; gg < 16; ++gg) {
            const float4 p = red_out[gg][c4];
            o.x += p.x; o.y += p.y; o.z += p.z; o.w += p.w;
        }
        ((float4*)(out + (size_t)bh * DV))[cb * 8 + c4] = o;
    }
}

extern "C" void kernel_launch(void* const* d_in, const int* in_sizes, int n_in,
                              void* d_out, int out_size)
{
    const float* q     = (const float*)d_in[0];  // (B,H,1,Dk)
    const float* k     = (const float*)d_in[1];  // (B,H,1,Dk)
    const float* v     = (const float*)d_in[2];  // (B,H,1,Dv)
    const float* g     = (const float*)d_in[3];  // (B,H,1)
    const float* beta  = (const float*)d_in[4];  // (B,H,1)
    const float* state = (const float*)d_in[5];  // (B,H,Dk,Dv)

    float* out       = (float*)d_out;            // first B*H*Dv floats
    float* state_out = out + (size_t)BH * DV;    // then B*H*Dk*Dv floats

    delta_cell_kernel<<<BH * 4, 128>>>(q, k, v, g, beta, state,
                                       out, state_out);
}